// round 7
// baseline (speedup 1.0000x reference)
#include <cuda_runtime.h>
#include <cuda_bf16.h>
#include <cstdint>

// PostProcessor: fused softmax(81) + rotated-box decode, N=200000 rows.
//   class_logits   : [N, 81]   f32
//   box_regression : [N, 405]  f32  (= [N, 81, 5])
//   proposal_boxes : [N, 5]    f32  (cx, cy, w, h, angle)
//   out            : [N, 486]  f32  (= [softmax(81) | decoded(405)])
//
// R5: R4 (bulk-copy staged, warp-per-row) plus two latency-tail fixes:
//  1. wait_group.READ 0 for the output bulk store — block retires once SMEM
//     is read, instead of waiting for global visibility (~600cyc/block).
//  2. Split mbarriers for logits vs reg tiles — softmax starts as soon as
//     the small logits tile (2592B) lands, overlapping the reg transfer.

#define PP_N    200000
#define PP_RPB  8
#define LOG_B   (PP_RPB * 81 * 4)    //  2592 bytes per block
#define REG_B   (PP_RPB * 405 * 4)   // 12960 bytes
#define OUT_B   (PP_RPB * 486 * 4)   // 15552 bytes

__device__ __forceinline__ uint32_t smem_u32(const void* p) {
    return (uint32_t)__cvta_generic_to_shared(p);
}

__device__ __forceinline__ void mbar_wait_p0(uint32_t mb) {
    uint32_t done;
    asm volatile(
        "{\n\t.reg .pred p;\n\t"
        "mbarrier.try_wait.parity.acquire.cta.shared::cta.b64 p, [%1], 0;\n\t"
        "selp.b32 %0, 1, 0, p;\n\t}"
        : "=r"(done) : "r"(mb) : "memory");
    if (!done) {
        asm volatile(
            "{\n\t.reg .pred P1;\n\t"
            "WAIT_LOOP_%=:\n\t"
            "mbarrier.try_wait.parity.acquire.cta.shared::cta.b64 P1, [%0], 0, 0x989680;\n\t"
            "@P1 bra.uni WAIT_DONE_%=;\n\t"
            "bra.uni WAIT_LOOP_%=;\n\t"
            "WAIT_DONE_%=:\n\t}"
            :: "r"(mb) : "memory");
    }
}

__global__ __launch_bounds__(256)
void PostProcessor_54374285967910_kernel(
    const float* __restrict__ logits,
    const float* __restrict__ reg,
    const float* __restrict__ boxes,
    float* __restrict__ out)
{
    __shared__ alignas(16) float s_log[PP_RPB * 81];    //  648 f
    __shared__ alignas(16) float s_reg[PP_RPB * 405];   // 3240 f
    __shared__ alignas(16) float s_out[PP_RPB * 486];   // 3888 f
    __shared__ alignas(8)  uint64_t s_mbar[2];          // [0]=logits [1]=reg

    const int tid  = (int)threadIdx.x;
    const int bid  = (int)blockIdx.x;
    const int warp = tid >> 5;
    const int lane = tid & 31;

    const uint32_t mbL = smem_u32(&s_mbar[0]);
    const uint32_t mbR = smem_u32(&s_mbar[1]);

    if (tid == 0) {
        asm volatile("mbarrier.init.shared::cta.b64 [%0], 1;" :: "r"(mbL) : "memory");
        asm volatile("mbarrier.init.shared::cta.b64 [%0], 1;" :: "r"(mbR) : "memory");
    }
    __syncthreads();   // inits visible before waits / TMA completions

    if (tid == 0) {
        asm volatile("mbarrier.arrive.expect_tx.shared::cta.b64 _, [%0], %1;"
                     :: "r"(mbL), "r"((uint32_t)LOG_B) : "memory");
        asm volatile(
            "cp.async.bulk.shared::cta.global.mbarrier::complete_tx::bytes [%0], [%1], %2, [%3];"
            :: "r"(smem_u32(s_log)),
               "l"(logits + (size_t)bid * (PP_RPB * 81)),
               "r"((uint32_t)LOG_B), "r"(mbL) : "memory");
        asm volatile("mbarrier.arrive.expect_tx.shared::cta.b64 _, [%0], %1;"
                     :: "r"(mbR), "r"((uint32_t)REG_B) : "memory");
        asm volatile(
            "cp.async.bulk.shared::cta.global.mbarrier::complete_tx::bytes [%0], [%1], %2, [%3];"
            :: "r"(smem_u32(s_reg)),
               "l"(reg + (size_t)bid * (PP_RPB * 405)),
               "r"((uint32_t)REG_B), "r"(mbR) : "memory");
    }

    // ---- per-row proposal params: in flight while bulk copies stream ----
    const int row = bid * PP_RPB + warp;
    const float cx = boxes[(size_t)row * 5 + 0];
    const float cy = boxes[(size_t)row * 5 + 1];
    const float bw = boxes[(size_t)row * 5 + 2];
    const float bh = boxes[(size_t)row * 5 + 3];
    const float ba = boxes[(size_t)row * 5 + 4];

    // ================= softmax: needs only the logits tile =================
    mbar_wait_p0(mbL);

    const float* __restrict__ lrow = s_log + warp * 81;
    float* __restrict__       orow = s_out + warp * 486;

    const bool  t2 = (lane < 17);
    const float x0 = lrow[lane];
    const float x1 = lrow[lane + 32];
    const float x2 = t2 ? lrow[lane + 64] : -3.402823466e38f;

    float m = fmaxf(fmaxf(x0, x1), x2);
    #pragma unroll
    for (int o = 16; o > 0; o >>= 1)
        m = fmaxf(m, __shfl_xor_sync(0xffffffffu, m, o));

    const float e0 = __expf(x0 - m);
    const float e1 = __expf(x1 - m);
    const float e2 = t2 ? __expf(x2 - m) : 0.0f;

    float s = e0 + e1 + e2;
    #pragma unroll
    for (int o = 16; o > 0; o >>= 1)
        s += __shfl_xor_sync(0xffffffffu, s, o);

    const float inv = __fdividef(1.0f, s);
    orow[lane]      = e0 * inv;
    orow[lane + 32] = e1 * inv;
    if (t2) orow[lane + 64] = e2 * inv;

    // ================= decode: needs the reg tile =================
    mbar_wait_p0(mbR);

    const float* __restrict__ rrow = s_reg + warp * 405;
    const float CLIP    = 4.135166556742356f;   // log(1000/16)
    const float RAD2DEG = 57.29577951308232f;   // 180/pi

    #pragma unroll
    for (int g = 0; g < 3; ++g) {
        if (g == 2 && !t2) break;
        const int anchor = lane + 32 * g;   // lane*5 mod 32 perm -> no conflicts
        const float* p = rrow + anchor * 5;
        const float a0 = p[0], a1 = p[1], a2 = p[2], a3 = p[3], a4 = p[4];
        float* q = orow + 81 + anchor * 5;
        q[0] = fminf(fmaxf(fmaf(a0 * 0.1f, bw, cx), 0.0f), 1023.0f);
        q[1] = fminf(fmaxf(fmaf(a1 * 0.1f, bh, cy), 0.0f), 1023.0f);
        q[2] = __expf(fminf(a2 * 0.2f, CLIP)) * bw;
        q[3] = __expf(fminf(a3 * 0.2f, CLIP)) * bh;
        q[4] = fmaf(a4, RAD2DEG, ba);
    }

    __syncthreads();   // all s_out writes done before bulk store reads them

    // ---- drain output: one bulk store; wait only for SMEM READ completion ----
    if (tid == 0) {
        asm volatile("fence.proxy.async.shared::cta;" ::: "memory");
        asm volatile(
            "cp.async.bulk.global.shared::cta.bulk_group [%0], [%1], %2;"
            :: "l"(out + (size_t)bid * (PP_RPB * 486)),
               "r"(smem_u32(s_out)), "r"((uint32_t)OUT_B) : "memory");
        asm volatile("cp.async.bulk.commit_group;" ::: "memory");
        asm volatile("cp.async.bulk.wait_group.read 0;" ::: "memory");
    }
}

extern "C" void kernel_launch(void* const* d_in, const int* in_sizes, int n_in,
                              void* d_out, int out_size)
{
    const float* logits = (const float*)d_in[0];   // [N, 81]
    const float* reg    = (const float*)d_in[1];   // [N, 405]
    const float* boxes  = (const float*)d_in[2];   // [N, 5]
    float*       out    = (float*)d_out;           // [N, 486]

    const int blocks = PP_N / PP_RPB;              // 25000, exact
    PostProcessor_54374285967910_kernel<<<blocks, 256>>>(logits, reg, boxes, out);
}

// round 13
// speedup vs baseline: 1.0127x; 1.0127x over previous
#include <cuda_runtime.h>
#include <cuda_bf16.h>
#include <cstdint>

// PostProcessor: fused softmax(81) + rotated-box decode, N=200000 rows.
//   class_logits   : [N, 81]   f32
//   box_regression : [N, 405]  f32  (= [N, 81, 5])
//   proposal_boxes : [N, 5]    f32  (cx, cy, w, h, angle)
//   out            : [N, 486]  f32  (= [softmax(81) | decoded(405)])
//
// R12: larger-tile retry WITHOUT the risky >48KB dynamic-SMEM config that
// failed the container twice. RPB=12 rows/block, 384 threads, 46.7KB STATIC
// smem (no cudaFuncSetAttribute). 16667 blocks; the last block covers only
// 8 rows via runtime bulk-copy sizes (8*81*4 etc. remain 16B multiples).
// Structure otherwise identical to the proven R4: single mbarrier,
// cp.async.bulk staged in/out, warp-per-row compute.

#define PP_N    200000
#define PP_RPB  12
#define LOG_F   (PP_RPB * 81)        //  972 floats
#define REG_F   (PP_RPB * 405)       // 4860 floats
#define OUT_F   (PP_RPB * 486)       // 5832 floats
// static smem total: (972+4860+5832)*4 + 16 = 46672 B  (< 48KB, no opt-in)

__device__ __forceinline__ uint32_t smem_u32(const void* p) {
    return (uint32_t)__cvta_generic_to_shared(p);
}

__global__ __launch_bounds__(384)
void PostProcessor_54374285967910_kernel(
    const float* __restrict__ logits,
    const float* __restrict__ reg,
    const float* __restrict__ boxes,
    float* __restrict__ out)
{
    __shared__ alignas(16) float s_log[LOG_F];
    __shared__ alignas(16) float s_reg[REG_F];
    __shared__ alignas(16) float s_out[OUT_F];
    __shared__ alignas(8)  uint64_t s_mbar;

    const int tid  = (int)threadIdx.x;
    const int bid  = (int)blockIdx.x;
    const int warp = tid >> 5;              // 0..11, warp w owns row w
    const int lane = tid & 31;

    const int row0  = bid * PP_RPB;
    const int nrows = (PP_N - row0 < PP_RPB) ? (PP_N - row0) : PP_RPB;  // 12, or 8 in last block
    const uint32_t log_b = (uint32_t)(nrows * 81 * 4);   // 16B multiple (nrows%4==0)
    const uint32_t reg_b = (uint32_t)(nrows * 405 * 4);
    const uint32_t out_b = (uint32_t)(nrows * 486 * 4);

    const uint32_t mb = smem_u32(&s_mbar);

    if (tid == 0) {
        asm volatile("mbarrier.init.shared::cta.b64 [%0], 1;" :: "r"(mb) : "memory");
    }
    __syncthreads();   // init visible before waits / TMA completions

    if (tid == 0) {
        asm volatile("mbarrier.arrive.expect_tx.shared::cta.b64 _, [%0], %1;"
                     :: "r"(mb), "r"(log_b + reg_b) : "memory");
        asm volatile(
            "cp.async.bulk.shared::cta.global.mbarrier::complete_tx::bytes [%0], [%1], %2, [%3];"
            :: "r"(smem_u32(s_log)),
               "l"(logits + (size_t)row0 * 81),
               "r"(log_b), "r"(mb) : "memory");
        asm volatile(
            "cp.async.bulk.shared::cta.global.mbarrier::complete_tx::bytes [%0], [%1], %2, [%3];"
            :: "r"(smem_u32(s_reg)),
               "l"(reg + (size_t)row0 * 405),
               "r"(reg_b), "r"(mb) : "memory");
    }

    // ---- per-row proposal params: load while bulk copies stream ----
    const int  row   = row0 + warp;
    const bool valid = (warp < nrows);
    float cx = 0.f, cy = 0.f, bw = 0.f, bh = 0.f, ba = 0.f;
    if (valid) {
        cx = boxes[(size_t)row * 5 + 0];
        cy = boxes[(size_t)row * 5 + 1];
        bw = boxes[(size_t)row * 5 + 2];
        bh = boxes[(size_t)row * 5 + 3];
        ba = boxes[(size_t)row * 5 + 4];
    }

    // ---- wait for bulk loads (phase parity 0, acquire) ----
    {
        uint32_t done;
        asm volatile(
            "{\n\t.reg .pred p;\n\t"
            "mbarrier.try_wait.parity.acquire.cta.shared::cta.b64 p, [%1], 0;\n\t"
            "selp.b32 %0, 1, 0, p;\n\t}"
            : "=r"(done) : "r"(mb) : "memory");
        if (!done) {
            asm volatile(
                "{\n\t.reg .pred P1;\n\t"
                "WAIT_LOOP_%=:\n\t"
                "mbarrier.try_wait.parity.acquire.cta.shared::cta.b64 P1, [%0], 0, 0x989680;\n\t"
                "@P1 bra.uni WAIT_DONE_%=;\n\t"
                "bra.uni WAIT_LOOP_%=;\n\t"
                "WAIT_DONE_%=:\n\t}"
                :: "r"(mb) : "memory");
        }
    }

    // ---------------- compute: warp w owns row w (warp-local only) ----------
    if (valid) {
        const float* __restrict__ lrow = s_log + warp * 81;
        const float* __restrict__ rrow = s_reg + warp * 405;
        float* __restrict__       orow = s_out + warp * 486;

        // softmax over 81 logits (lanes cover {lane, lane+32, lane+64(<17)})
        const bool  t2 = (lane < 17);
        const float x0 = lrow[lane];
        const float x1 = lrow[lane + 32];
        const float x2 = t2 ? lrow[lane + 64] : -3.402823466e38f;

        float m = fmaxf(fmaxf(x0, x1), x2);
        #pragma unroll
        for (int o = 16; o > 0; o >>= 1)
            m = fmaxf(m, __shfl_xor_sync(0xffffffffu, m, o));

        const float e0 = __expf(x0 - m);
        const float e1 = __expf(x1 - m);
        const float e2 = t2 ? __expf(x2 - m) : 0.0f;

        float s = e0 + e1 + e2;
        #pragma unroll
        for (int o = 16; o > 0; o >>= 1)
            s += __shfl_xor_sync(0xffffffffu, s, o);

        const float inv = __fdividef(1.0f, s);
        orow[lane]      = e0 * inv;
        orow[lane + 32] = e1 * inv;
        if (t2) orow[lane + 64] = e2 * inv;

        // decode: lane owns anchors {lane, lane+32, lane+64(<17)}, 5 floats
        // each (lane*5 mod 32 is a permutation -> conflict-free SMEM)
        const float CLIP    = 4.135166556742356f;   // log(1000/16)
        const float RAD2DEG = 57.29577951308232f;   // 180/pi

        #pragma unroll
        for (int g = 0; g < 3; ++g) {
            if (g == 2 && !t2) break;
            const int anchor = lane + 32 * g;
            const float* p = rrow + anchor * 5;
            const float a0 = p[0], a1 = p[1], a2 = p[2], a3 = p[3], a4 = p[4];
            float* q = orow + 81 + anchor * 5;
            q[0] = fminf(fmaxf(fmaf(a0 * 0.1f, bw, cx), 0.0f), 1023.0f);
            q[1] = fminf(fmaxf(fmaf(a1 * 0.1f, bh, cy), 0.0f), 1023.0f);
            q[2] = __expf(fminf(a2 * 0.2f, CLIP)) * bw;
            q[3] = __expf(fminf(a3 * 0.2f, CLIP)) * bh;
            q[4] = fmaf(a4, RAD2DEG, ba);
        }
    }

    __syncthreads();   // all s_out writes done before bulk store reads them

    // ---- drain output: one bulk store; wait only for SMEM read ----
    if (tid == 0) {
        asm volatile("fence.proxy.async.shared::cta;" ::: "memory");
        asm volatile(
            "cp.async.bulk.global.shared::cta.bulk_group [%0], [%1], %2;"
            :: "l"(out + (size_t)row0 * 486),
               "r"(smem_u32(s_out)), "r"(out_b) : "memory");
        asm volatile("cp.async.bulk.commit_group;" ::: "memory");
        asm volatile("cp.async.bulk.wait_group.read 0;" ::: "memory");
    }
}

extern "C" void kernel_launch(void* const* d_in, const int* in_sizes, int n_in,
                              void* d_out, int out_size)
{
    const float* logits = (const float*)d_in[0];   // [N, 81]
    const float* reg    = (const float*)d_in[1];   // [N, 405]
    const float* boxes  = (const float*)d_in[2];   // [N, 5]
    float*       outp   = (float*)d_out;           // [N, 486]

    const int blocks = (PP_N + PP_RPB - 1) / PP_RPB;   // 16667 (last block: 8 rows)
    PostProcessor_54374285967910_kernel<<<blocks, 384>>>(logits, reg, boxes, outp);
}